// round 4
// baseline (speedup 1.0000x reference)
#include <cuda_runtime.h>

#define EPSF 1e-8f
#define DEG2RAD 0.017453292519943295f

__device__ double g_num;
__device__ double g_den;
__device__ int    g_mask4;

// ---------------------------------------------------------------------------
// Kernel 0: reset accumulators / detection state
// ---------------------------------------------------------------------------
__global__ void rot_reset_kernel() {
    g_num = 0.0;
    g_den = 0.0;
    g_mask4 = 0;
}

// ---------------------------------------------------------------------------
// Kernel 1: detect pos_idx storage layout.
// Scans the first n BYTES (safe for u8 / i32 / f32 backing buffers) and
// records which byte residues (mod 4) ever hold a nonzero byte.
//   residue pattern 0b0001 -> int32 {0,1}
//   residue pattern 0b1100 -> float32 {0.0,1.0} (bytes 0x80,0x3f at off 2,3)
//   anything else / all-zero -> uint8/bool (always-safe fallback)
// ---------------------------------------------------------------------------
__global__ void rot_detect_kernel(const unsigned char* __restrict__ p, int nbytes) {
    int nw = nbytes >> 2;
    const unsigned* w = (const unsigned*)p;
    unsigned pat = 0;
    for (int idx = blockIdx.x * blockDim.x + threadIdx.x; idx < nw;
         idx += gridDim.x * blockDim.x) {
        unsigned v = w[idx];
        if (v & 0x000000FFu) pat |= 1u;
        if (v & 0x0000FF00u) pat |= 2u;
        if (v & 0x00FF0000u) pat |= 4u;
        if (v & 0xFF000000u) pat |= 8u;
    }
    #pragma unroll
    for (int o = 16; o > 0; o >>= 1)
        pat |= __shfl_down_sync(0xffffffffu, pat, o);
    if ((threadIdx.x & 31) == 0 && pat)
        atomicOr(&g_mask4, (int)pat);
}

// ---------------------------------------------------------------------------
// Kernel 2: main — per-pair rotated IoU + partial loss reduction
// ---------------------------------------------------------------------------
__global__ void __launch_bounds__(128)
rot_iou_kernel(const float* __restrict__ pred,
               const float* __restrict__ target,
               const void*  __restrict__ pos,
               float* __restrict__ out_iou,
               int n)
{
    int i = blockIdx.x * blockDim.x + threadIdx.x;
    float lnum = 0.0f;
    int   lden = 0;

    if (i < n) {
        const float* p = pred   + 5 * i;
        const float* t = target + 5 * i;

        float x1 = p[0], y1 = p[1], w1 = p[2], h1 = p[3];
        float a1 = p[4] * DEG2RAD;
        float x2 = t[0], y2 = t[1], w2 = t[2], h2 = t[3];
        float a2 = (t[4] * 180.0f - 180.0f) * DEG2RAD;

        float s1, co1, s2, co2;
        sincosf(a1, &s1, &co1);
        sincosf(a2, &s2, &co2);

        const float XS[4] = { 0.5f, -0.5f, -0.5f,  0.5f };
        const float YS[4] = { 0.5f,  0.5f, -0.5f, -0.5f };
        float c1x[4], c1y[4], c2x[4], c2y[4];
        #pragma unroll
        for (int k = 0; k < 4; k++) {
            float xw = XS[k] * w1, yh = YS[k] * h1;
            c1x[k] = xw * co1 - yh * s1 + x1;
            c1y[k] = xw * s1  + yh * co1 + y1;
            xw = XS[k] * w2; yh = YS[k] * h2;
            c2x[k] = xw * co2 - yh * s2 + x2;
            c2y[k] = xw * s2  + yh * co2 + y2;
        }

        // point-in-box masks (tol matches reference)
        bool m1[4], m2[4];
        {
            float ax = c2x[0], ay = c2y[0];
            float abx = c2x[1] - ax, aby = c2y[1] - ay;
            float adx = c2x[3] - ax, ady = c2y[3] - ay;
            float ab2 = abx * abx + aby * aby + EPSF;
            float ad2 = adx * adx + ady * ady + EPSF;
            #pragma unroll
            for (int k = 0; k < 4; k++) {
                float amx = c1x[k] - ax, amy = c1y[k] - ay;
                float pab = (abx * amx + aby * amy) / ab2;
                float pad = (adx * amx + ady * amy) / ad2;
                m1[k] = (pab > -1e-6f) && (pab < 1.0f + 1e-6f) &&
                        (pad > -1e-6f) && (pad < 1.0f + 1e-6f);
            }
        }
        {
            float ax = c1x[0], ay = c1y[0];
            float abx = c1x[1] - ax, aby = c1y[1] - ay;
            float adx = c1x[3] - ax, ady = c1y[3] - ay;
            float ab2 = abx * abx + aby * aby + EPSF;
            float ad2 = adx * adx + ady * ady + EPSF;
            #pragma unroll
            for (int k = 0; k < 4; k++) {
                float amx = c2x[k] - ax, amy = c2y[k] - ay;
                float pab = (abx * amx + aby * amy) / ab2;
                float pad = (adx * amx + ady * amy) / ad2;
                m2[k] = (pab > -1e-6f) && (pab < 1.0f + 1e-6f) &&
                        (pad > -1e-6f) && (pad < 1.0f + 1e-6f);
            }
        }

        // compact valid vertices (corners inside + edge intersections)
        float lx[24], ly[24];
        int cnt = 0;
        float sx = 0.0f, sy = 0.0f;
        #pragma unroll
        for (int k = 0; k < 4; k++)
            if (m1[k]) { lx[cnt] = c1x[k]; ly[cnt] = c1y[k]; sx += c1x[k]; sy += c1y[k]; cnt++; }
        #pragma unroll
        for (int k = 0; k < 4; k++)
            if (m2[k]) { lx[cnt] = c2x[k]; ly[cnt] = c2y[k]; sx += c2x[k]; sy += c2y[k]; cnt++; }

        float rX[4], rY[4], sX[4], sY[4];
        #pragma unroll
        for (int k = 0; k < 4; k++) {
            rX[k] = c1x[(k + 1) & 3] - c1x[k];
            rY[k] = c1y[(k + 1) & 3] - c1y[k];
            sX[k] = c2x[(k + 1) & 3] - c2x[k];
            sY[k] = c2y[(k + 1) & 3] - c2y[k];
        }
        #pragma unroll
        for (int e1 = 0; e1 < 4; e1++) {
            #pragma unroll
            for (int e2 = 0; e2 < 4; e2++) {
                float qpx = c2x[e2] - c1x[e1];
                float qpy = c2y[e2] - c1y[e1];
                float den = rX[e1] * sY[e2] - rY[e1] * sX[e2] + EPSF;
                float tt  = (qpx * sY[e2] - qpy * sX[e2]) / den;
                float uu  = (qpx * rY[e1] - qpy * rX[e1]) / den;
                if (tt > 0.0f && tt < 1.0f && uu > 0.0f && uu < 1.0f) {
                    float px = c1x[e1] + tt * rX[e1];
                    float py = c1y[e1] + tt * rY[e1];
                    lx[cnt] = px; ly[cnt] = py; sx += px; sy += py; cnt++;
                }
            }
        }

        // convex area over valid vertices (diamond-angle sort == atan2 order)
        float inter = 0.0f;
        if (cnt >= 3) {
            float mx = sx / (float)cnt;
            float my = sy / (float)cnt;
            float key[24];
            for (int k = 0; k < cnt; k++) {
                float vx = lx[k] - mx;
                float vy = ly[k] - my;
                lx[k] = vx; ly[k] = vy;
                float d = fabsf(vx) + fabsf(vy);
                float r = (d > 0.0f) ? (vx / d) : 0.0f;
                key[k] = (vy >= 0.0f) ? (1.0f - r) : (r - 1.0f);
            }
            // stable insertion sort (ties keep original order, as jnp.argsort)
            for (int k = 1; k < cnt; k++) {
                float kk = key[k], vx = lx[k], vy = ly[k];
                int j = k - 1;
                while (j >= 0 && key[j] > kk) {
                    key[j + 1] = key[j];
                    lx[j + 1]  = lx[j];
                    ly[j + 1]  = ly[j];
                    j--;
                }
                key[j + 1] = kk; lx[j + 1] = vx; ly[j + 1] = vy;
            }
            float cr = 0.0f;
            for (int k = 0; k < cnt; k++) {
                int k2 = (k + 1 == cnt) ? 0 : (k + 1);
                cr += lx[k] * ly[k2] - ly[k] * lx[k2];
            }
            inter = 0.5f * fabsf(cr);
        }

        float area1 = w1 * h1;
        float area2 = w2 * h2;
        float iou = inter / (area1 + area2 - inter + EPSF);
        iou = fminf(fmaxf(iou, 1e-7f), 1.0f - 1e-7f);
        out_iou[i] = iou;

        // mask read per detected layout (uniform branch)
        int m4 = g_mask4;
        bool mm;
        if (m4 == 1)        mm = (((const int*)pos)[i] != 0);
        else if (m4 == 12)  mm = (((const float*)pos)[i] != 0.0f);
        else                mm = (((const unsigned char*)pos)[i] != 0);
        if (mm) { lnum = 1.0f - iou; lden = 1; }
    }

    // warp reduce
    #pragma unroll
    for (int o = 16; o > 0; o >>= 1) {
        lnum += __shfl_down_sync(0xffffffffu, lnum, o);
        lden += __shfl_down_sync(0xffffffffu, lden, o);
    }
    __shared__ float snum[4];
    __shared__ int   sden[4];
    int wid = threadIdx.x >> 5;
    if ((threadIdx.x & 31) == 0) { snum[wid] = lnum; sden[wid] = lden; }
    __syncthreads();
    if (threadIdx.x == 0) {
        float bn = snum[0] + snum[1] + snum[2] + snum[3];
        int   bd = sden[0] + sden[1] + sden[2] + sden[3];
        if (bn != 0.0f) atomicAdd(&g_num, (double)bn);
        if (bd != 0)    atomicAdd(&g_den, (double)bd);
    }
}

// ---------------------------------------------------------------------------
// Kernel 3: finalize loss
// ---------------------------------------------------------------------------
__global__ void rot_finalize_kernel(float* out, int has_loss) {
    if (has_loss) {
        double d = g_den > 1.0 ? g_den : 1.0;
        out[0] = (float)(g_num / d);
    }
}

// ---------------------------------------------------------------------------
extern "C" void kernel_launch(void* const* d_in, const int* in_sizes, int n_in,
                              void* d_out, int out_size)
{
    const float* pred   = (const float*)d_in[0];
    const float* target = (const float*)d_in[1];
    const void*  pos    = d_in[2];
    int n = in_sizes[2];               // pos_idx element count = B*A*W*H

    float* out = (float*)d_out;
    int has_loss = (out_size > n) ? 1 : 0;
    float* out_iou = out + (has_loss ? 1 : 0);

    rot_reset_kernel<<<1, 1>>>();
    rot_detect_kernel<<<96, 256>>>((const unsigned char*)pos, n);

    int threads = 128;
    int blocks  = (n + threads - 1) / threads;
    rot_iou_kernel<<<blocks, threads>>>(pred, target, pos, out_iou, n);

    rot_finalize_kernel<<<1, 1>>>(out, has_loss);
}